// round 4
// baseline (speedup 1.0000x reference)
#include <cuda_runtime.h>
#include <math.h>

#define E_DIM   1024
#define S_LEN   2048
#define N_BATCH 2
#define N_HEADS 16
#define H_DIM   64
#define M_ROWS  (N_BATCH * S_LEN)   // 4096

// Scratch (allocation-free): projected Q/K/V and attention output, [B,S,H*D] fp32.
__device__ float g_q[(size_t)M_ROWS * E_DIM];
__device__ float g_k[(size_t)M_ROWS * E_DIM];
__device__ float g_v[(size_t)M_ROWS * E_DIM];
__device__ float g_o[(size_t)M_ROWS * E_DIM];

// ===================== GEMM: Y = X @ W^T + b =====================
// X: [M,1024] row-major, W: [1024,1024] row-major (out,in), b: [1024].
// 128x128x16 block tile, 8x8 per thread, 256 threads.
#define GBM 128
#define GBN 128
#define GBK 16
#define GS  132   // padded smem stride (floats), keeps float4 alignment, kills STS conflicts

__global__ __launch_bounds__(256) void gemm_bias_kernel(
    const float* __restrict__ X0, const float* __restrict__ X1, const float* __restrict__ X2,
    const float* __restrict__ W0, const float* __restrict__ W1, const float* __restrict__ W2,
    const float* __restrict__ B0, const float* __restrict__ B1, const float* __restrict__ B2,
    float* __restrict__ Y0, float* __restrict__ Y1, float* __restrict__ Y2)
{
    const int z = blockIdx.z;
    const float* __restrict__ X  = (z == 0) ? X0 : ((z == 1) ? X1 : X2);
    const float* __restrict__ W  = (z == 0) ? W0 : ((z == 1) ? W1 : W2);
    const float* __restrict__ Bv = (z == 0) ? B0 : ((z == 1) ? B1 : B2);
    float* __restrict__ Y        = (z == 0) ? Y0 : ((z == 1) ? Y1 : Y2);

    __shared__ float As[GBK * GS];   // As[k][m], transposed
    __shared__ float Bs[GBK * GS];   // Bs[k][n], transposed

    const int tid = threadIdx.x;
    const int m0 = blockIdx.y * GBM;
    const int n0 = blockIdx.x * GBN;
    const int tx = tid & 15;   // 0..15 -> 8 cols each
    const int ty = tid >> 4;   // 0..15 -> 8 rows each

    float acc[8][8];
#pragma unroll
    for (int i = 0; i < 8; ++i)
#pragma unroll
        for (int j = 0; j < 8; ++j) acc[i][j] = 0.f;

    for (int k0 = 0; k0 < E_DIM; k0 += GBK) {
#pragma unroll
        for (int l = 0; l < 2; ++l) {
            int idx = tid + l * 256;        // 0..511
            int row = idx >> 2;             // 0..127
            int c4  = idx & 3;              // 0..3 (float4 slot within 16-wide k tile)
            float4 av = *(const float4*)&X[(size_t)(m0 + row) * E_DIM + k0 + c4 * 4];
            As[(c4 * 4 + 0) * GS + row] = av.x;
            As[(c4 * 4 + 1) * GS + row] = av.y;
            As[(c4 * 4 + 2) * GS + row] = av.z;
            As[(c4 * 4 + 3) * GS + row] = av.w;
            float4 wv = *(const float4*)&W[(size_t)(n0 + row) * E_DIM + k0 + c4 * 4];
            Bs[(c4 * 4 + 0) * GS + row] = wv.x;
            Bs[(c4 * 4 + 1) * GS + row] = wv.y;
            Bs[(c4 * 4 + 2) * GS + row] = wv.z;
            Bs[(c4 * 4 + 3) * GS + row] = wv.w;
        }
        __syncthreads();

#pragma unroll
        for (int kk = 0; kk < GBK; ++kk) {
            float a[8], b[8];
            *(float4*)&a[0] = *(const float4*)&As[kk * GS + ty * 8];
            *(float4*)&a[4] = *(const float4*)&As[kk * GS + ty * 8 + 4];
            *(float4*)&b[0] = *(const float4*)&Bs[kk * GS + tx * 8];
            *(float4*)&b[4] = *(const float4*)&Bs[kk * GS + tx * 8 + 4];
#pragma unroll
            for (int i = 0; i < 8; ++i)
#pragma unroll
                for (int j = 0; j < 8; ++j)
                    acc[i][j] = fmaf(a[i], b[j], acc[i][j]);
        }
        __syncthreads();
    }

    float bias[8];
#pragma unroll
    for (int j = 0; j < 8; ++j) bias[j] = Bv[n0 + tx * 8 + j];

#pragma unroll
    for (int i = 0; i < 8; ++i) {
        float* yrow = &Y[(size_t)(m0 + ty * 8 + i) * E_DIM + n0 + tx * 8];
        float4 r0 = make_float4(acc[i][0] + bias[0], acc[i][1] + bias[1],
                                acc[i][2] + bias[2], acc[i][3] + bias[3]);
        float4 r1 = make_float4(acc[i][4] + bias[4], acc[i][5] + bias[5],
                                acc[i][6] + bias[6], acc[i][7] + bias[7]);
        *(float4*)&yrow[0] = r0;
        *(float4*)&yrow[4] = r1;
    }
}

// ===================== Flash attention (causal) =====================
// One block per (b, h, 64-row q tile). 256 threads: rg=tid/16 owns rows rg*4..+3,
// cg=tid%16 owns cols cg*4..+3 (score cols / output dims). Q/K/V tiles are 64x64
// fp32 in smem with XOR swizzle (col4 ^= (row>>2)&7) -> conflict-free LDS.128
// for both the tile stores and the column-varying score reads. P tile [64][68].
#define ATTN_SMEM (3 * 64 * 64 * 4 + 64 * 68 * 4)   // 66560 B

__global__ __launch_bounds__(256) void attn_kernel(
    const float* __restrict__ Qp, const float* __restrict__ Kp,
    const float* __restrict__ Vp, float* __restrict__ Op)
{
    extern __shared__ float sm[];
    float* Qs = sm;                // 64*64 swizzled
    float* Ks = sm + 64 * 64;      // 64*64 swizzled
    float* Vs = sm + 2 * 64 * 64;  // 64*64 swizzled
    float* Ps = sm + 3 * 64 * 64;  // 64*68 (padded)

    const int i  = blockIdx.x;     // q tile (0..31)
    const int bh = blockIdx.y;     // 0..31
    const int b  = bh >> 4;
    const int h  = bh & 15;
    const int tid = threadIdx.x;
    const int rg = tid >> 4;       // 0..15
    const int cg = tid & 15;       // 0..15

    const size_t base = (size_t)b * S_LEN * E_DIM + (size_t)h * H_DIM;

    // Load Q tile (64 rows x 64 dims), swizzled.
#pragma unroll
    for (int l = 0; l < 4; ++l) {
        int idx = tid + l * 256;            // 0..1023
        int row = idx >> 4;                 // 0..63
        int c4  = idx & 15;                 // 0..15
        float4 v = *(const float4*)&Qp[base + (size_t)(i * 64 + row) * E_DIM + c4 * 4];
        int sc4 = c4 ^ ((row >> 2) & 7);
        *(float4*)&Qs[row * 64 + sc4 * 4] = v;
    }

    float m_prev[4], l_sum[4], o[4][4];
#pragma unroll
    for (int a = 0; a < 4; ++a) {
        m_prev[a] = -INFINITY;
        l_sum[a] = 0.f;
#pragma unroll
        for (int bb = 0; bb < 4; ++bb) o[a][bb] = 0.f;
    }

    for (int j = 0; j <= i; ++j) {
        __syncthreads();   // prior-iter Vs/Ps reads done before overwrite
#pragma unroll
        for (int l = 0; l < 4; ++l) {
            int idx = tid + l * 256;
            int row = idx >> 4;
            int c4  = idx & 15;
            int sc4 = c4 ^ ((row >> 2) & 7);
            float4 kv4 = *(const float4*)&Kp[base + (size_t)(j * 64 + row) * E_DIM + c4 * 4];
            *(float4*)&Ks[row * 64 + sc4 * 4] = kv4;
            float4 vv4 = *(const float4*)&Vp[base + (size_t)(j * 64 + row) * E_DIM + c4 * 4];
            *(float4*)&Vs[row * 64 + sc4 * 4] = vv4;
        }
        __syncthreads();

        // ---- scores: acc[a][bb] = <Q[rg*4+a,:], K[cg*4+bb,:]> ----
        float acc[4][4];
#pragma unroll
        for (int a = 0; a < 4; ++a)
#pragma unroll
            for (int bb = 0; bb < 4; ++bb) acc[a][bb] = 0.f;

#pragma unroll
        for (int d4 = 0; d4 < 16; ++d4) {
            float4 qv[4], kv[4];
#pragma unroll
            for (int a = 0; a < 4; ++a)
                qv[a] = *(const float4*)&Qs[(rg * 4 + a) * 64 + (d4 ^ (rg & 7)) * 4];
#pragma unroll
            for (int bb = 0; bb < 4; ++bb)
                kv[bb] = *(const float4*)&Ks[(cg * 4 + bb) * 64 + (d4 ^ (cg & 7)) * 4];
#pragma unroll
            for (int a = 0; a < 4; ++a)
#pragma unroll
                for (int bb = 0; bb < 4; ++bb) {
                    acc[a][bb] = fmaf(qv[a].x, kv[bb].x, acc[a][bb]);
                    acc[a][bb] = fmaf(qv[a].y, kv[bb].y, acc[a][bb]);
                    acc[a][bb] = fmaf(qv[a].z, kv[bb].z, acc[a][bb]);
                    acc[a][bb] = fmaf(qv[a].w, kv[bb].w, acc[a][bb]);
                }
        }

        // ---- online softmax (row reductions across the 16 lanes of each row group) ----
        const bool diag = (j == i);
#pragma unroll
        for (int a = 0; a < 4; ++a) {
            float mloc = -INFINITY;
#pragma unroll
            for (int bb = 0; bb < 4; ++bb) {
                float s = acc[a][bb] * 0.125f;   // 1/sqrt(64)
                if (diag && (cg * 4 + bb) > (rg * 4 + a)) s = -INFINITY;
                acc[a][bb] = s;
                mloc = fmaxf(mloc, s);
            }
            mloc = fmaxf(mloc, __shfl_xor_sync(0xffffffffu, mloc, 1));
            mloc = fmaxf(mloc, __shfl_xor_sync(0xffffffffu, mloc, 2));
            mloc = fmaxf(mloc, __shfl_xor_sync(0xffffffffu, mloc, 4));
            mloc = fmaxf(mloc, __shfl_xor_sync(0xffffffffu, mloc, 8));

            float m_new = fmaxf(m_prev[a], mloc);
            float fac = (m_prev[a] == -INFINITY) ? 0.f : __expf(m_prev[a] - m_new);
            m_prev[a] = m_new;

            float ls = 0.f;
#pragma unroll
            for (int bb = 0; bb < 4; ++bb) {
                float p = __expf(acc[a][bb] - m_new);
                acc[a][bb] = p;
                ls += p;
            }
            ls += __shfl_xor_sync(0xffffffffu, ls, 1);
            ls += __shfl_xor_sync(0xffffffffu, ls, 2);
            ls += __shfl_xor_sync(0xffffffffu, ls, 4);
            ls += __shfl_xor_sync(0xffffffffu, ls, 8);

            l_sum[a] = l_sum[a] * fac + ls;
#pragma unroll
            for (int bb = 0; bb < 4; ++bb) o[a][bb] *= fac;

            *(float4*)&Ps[(rg * 4 + a) * 68 + cg * 4] =
                make_float4(acc[a][0], acc[a][1], acc[a][2], acc[a][3]);
        }
        __syncwarp();   // P rows are exchanged only within the owning half-warp

        // ---- PV: o[a][bb] += sum_jj P[rg*4+a][jj] * V[jj][cg*4+bb] ----
#pragma unroll 4
        for (int jj = 0; jj < 64; ++jj) {
            float4 vv = *(const float4*)&Vs[jj * 64 + (cg ^ ((jj >> 2) & 7)) * 4];
            float p0 = Ps[(rg * 4 + 0) * 68 + jj];
            float p1 = Ps[(rg * 4 + 1) * 68 + jj];
            float p2 = Ps[(rg * 4 + 2) * 68 + jj];
            float p3 = Ps[(rg * 4 + 3) * 68 + jj];
            o[0][0] = fmaf(p0, vv.x, o[0][0]); o[0][1] = fmaf(p0, vv.y, o[0][1]);
            o[0][2] = fmaf(p0, vv.z, o[0][2]); o[0][3] = fmaf(p0, vv.w, o[0][3]);
            o[1][0] = fmaf(p1, vv.x, o[1][0]); o[1][1] = fmaf(p1, vv.y, o[1][1]);
            o[1][2] = fmaf(p1, vv.z, o[1][2]); o[1][3] = fmaf(p1, vv.w, o[1][3]);
            o[2][0] = fmaf(p2, vv.x, o[2][0]); o[2][1] = fmaf(p2, vv.y, o[2][1]);
            o[2][2] = fmaf(p2, vv.z, o[2][2]); o[2][3] = fmaf(p2, vv.w, o[2][3]);
            o[3][0] = fmaf(p3, vv.x, o[3][0]); o[3][1] = fmaf(p3, vv.y, o[3][1]);
            o[3][2] = fmaf(p3, vv.z, o[3][2]); o[3][3] = fmaf(p3, vv.w, o[3][3]);
        }
    }

    // ---- epilogue: normalize + store [B,S,H*D] ----
#pragma unroll
    for (int a = 0; a < 4; ++a) {
        float inv = 1.f / l_sum[a];
        float4 r = make_float4(o[a][0] * inv, o[a][1] * inv, o[a][2] * inv, o[a][3] * inv);
        *(float4*)&Op[base + (size_t)(i * 64 + rg * 4 + a) * E_DIM + cg * 4] = r;
    }
}

// ===================== launch =====================
extern "C" void kernel_launch(void* const* d_in, const int* in_sizes, int n_in,
                              void* d_out, int out_size)
{
    (void)in_sizes; (void)n_in; (void)out_size;
    const float* q  = (const float*)d_in[0];
    const float* k  = (const float*)d_in[1];
    const float* v  = (const float*)d_in[2];
    const float* Wq = (const float*)d_in[3];
    const float* bq = (const float*)d_in[4];
    const float* Wk = (const float*)d_in[5];
    const float* bk = (const float*)d_in[6];
    const float* Wv = (const float*)d_in[7];
    const float* bv = (const float*)d_in[8];
    const float* Wo = (const float*)d_in[9];
    const float* bo = (const float*)d_in[10];
    float* out = (float*)d_out;

    float *gq, *gk, *gv, *go;
    cudaGetSymbolAddress((void**)&gq, g_q);
    cudaGetSymbolAddress((void**)&gk, g_k);
    cudaGetSymbolAddress((void**)&gv, g_v);
    cudaGetSymbolAddress((void**)&go, g_o);

    // Fused Q/K/V projections (z selects the triple): 768 blocks.
    dim3 gridP(E_DIM / GBN, M_ROWS / GBM, 3);
    gemm_bias_kernel<<<gridP, 256>>>(q, k, v, Wq, Wk, Wv, bq, bk, bv, gq, gk, gv);

    // Causal flash attention.
    cudaFuncSetAttribute(attn_kernel, cudaFuncAttributeMaxDynamicSharedMemorySize, ATTN_SMEM);
    dim3 gridA(S_LEN / 64, N_BATCH * N_HEADS);
    attn_kernel<<<gridA, 256, ATTN_SMEM>>>(gq, gk, gv, go);

    // Output projection into d_out.
    dim3 gridO(E_DIM / GBN, M_ROWS / GBM, 1);
    gemm_bias_kernel<<<gridO, 256>>>(go, go, go, Wo, Wo, Wo, bo, bo, bo, out, out, out);
}

// round 6
// speedup vs baseline: 1.1334x; 1.1334x over previous
#include <cuda_runtime.h>
#include <math.h>
#include <stdint.h>

#define E_DIM   1024
#define S_LEN   2048
#define N_BATCH 2
#define N_HEADS 16
#define H_DIM   64
#define M_ROWS  (N_BATCH * S_LEN)   // 4096

// Scratch (allocation-free): projected Q/K/V and attention output, [B,S,H*D] fp32.
__device__ float g_q[(size_t)M_ROWS * E_DIM];
__device__ float g_k[(size_t)M_ROWS * E_DIM];
__device__ float g_v[(size_t)M_ROWS * E_DIM];
__device__ float g_o[(size_t)M_ROWS * E_DIM];

// ===================== helpers =====================
__device__ __forceinline__ uint32_t smem_u32(const void* p) {
    uint32_t a;
    asm("{ .reg .u64 t; cvta.to.shared.u64 t, %1; cvt.u32.u64 %0, t; }" : "=r"(a) : "l"(p));
    return a;
}
__device__ __forceinline__ uint32_t cvt_tf32(float f) {
    uint32_t u;
    asm("cvt.rna.tf32.f32 %0, %1;" : "=r"(u) : "f"(f));
    return u;
}

#define CP16(dst, src) \
    asm volatile("cp.async.cg.shared.global [%0], [%1], 16;" :: "r"(dst), "l"(src))
#define CPCOMMIT() asm volatile("cp.async.commit_group;" ::: "memory")
#define CPWAIT1()  asm volatile("cp.async.wait_group 1;" ::: "memory")

#define LDSM_X4(r0, r1, r2, r3, addr)                                          \
    asm volatile("ldmatrix.sync.aligned.m8n8.x4.shared.b16 {%0,%1,%2,%3}, [%4];" \
                 : "=r"(r0), "=r"(r1), "=r"(r2), "=r"(r3) : "r"(addr))
#define LDSM_X2(r0, r1, addr)                                                  \
    asm volatile("ldmatrix.sync.aligned.m8n8.x2.shared.b16 {%0,%1}, [%2];"     \
                 : "=r"(r0), "=r"(r1) : "r"(addr))

#define MMA_TF32(d, A, b0v, b1v)                                               \
    asm volatile("mma.sync.aligned.m16n8k8.row.col.f32.tf32.tf32.f32 "         \
                 "{%0,%1,%2,%3}, {%4,%5,%6,%7}, {%8,%9}, {%0,%1,%2,%3};"       \
                 : "+f"((d)[0]), "+f"((d)[1]), "+f"((d)[2]), "+f"((d)[3])      \
                 : "r"((A)[0]), "r"((A)[1]), "r"((A)[2]), "r"((A)[3]),         \
                   "r"(b0v), "r"(b1v))

// ===================== mma.sync TF32-split GEMM: Y = X @ W^T + b =====================
// CTA 128x128, 8 warps (2m x 4n), warp tile 64x32 (4 m16 tiles x 4 n8 tiles).
// K chunk = 16 (two k8 steps). Raw fp32 in smem via cp.async, 3-stage ring.
// Hi/lo tf32 split done at fragment time; 3 mma per logical mma (hihi,hilo,lohi).
#define NCHUNK   (E_DIM / 16)         // 64
#define STAGE_B  16384                // A 8KB + B 8KB (raw fp32)
#define GEMM_SMEM (3 * STAGE_B)       // 48 KB

__global__ __launch_bounds__(256) void gemm_tc_kernel(
    const float* __restrict__ X0, const float* __restrict__ X1, const float* __restrict__ X2,
    const float* __restrict__ W0, const float* __restrict__ W1, const float* __restrict__ W2,
    const float* __restrict__ B0, const float* __restrict__ B1, const float* __restrict__ B2,
    float* __restrict__ Y0, float* __restrict__ Y1, float* __restrict__ Y2)
{
    extern __shared__ char smem[];
    const int z = blockIdx.z;
    const float* __restrict__ X  = (z == 0) ? X0 : ((z == 1) ? X1 : X2);
    const float* __restrict__ W  = (z == 0) ? W0 : ((z == 1) ? W1 : W2);
    const float* __restrict__ Bv = (z == 0) ? B0 : ((z == 1) ? B1 : B2);
    float* __restrict__ Y        = (z == 0) ? Y0 : ((z == 1) ? Y1 : Y2);

    const int tid  = threadIdx.x;
    const int lane = tid & 31;
    const int wid  = tid >> 5;
    const int wm   = wid >> 2;   // 0..1 -> 64 rows
    const int wn   = wid & 3;    // 0..3 -> 32 cols
    const int m0 = blockIdx.y * 128;
    const int n0 = blockIdx.x * 128;

    const uint32_t sb = smem_u32(smem);

    // producer: 256 threads, 2 float4 per matrix per chunk.
    const int prow = tid >> 2;         // 0..63 (q=0), +64 (q=1)
    const int pc4  = tid & 3;
    const float* Xsrc = &X[(size_t)(m0 + prow) * E_DIM + pc4 * 4];
    const float* Wsrc = &W[(size_t)(n0 + prow) * E_DIM + pc4 * 4];
    const uint32_t pdst = sb + (uint32_t)prow * 64 + (uint32_t)pc4 * 16;

    #define CP_CHUNK(c, st) do {                                               \
        _Pragma("unroll")                                                      \
        for (int q = 0; q < 2; ++q) {                                          \
            uint32_t d = pdst + (uint32_t)(st) * STAGE_B + q * 4096;           \
            CP16(d,        Xsrc + (size_t)q * 64 * E_DIM + (c) * 16);          \
            CP16(d + 8192, Wsrc + (size_t)q * 64 * E_DIM + (c) * 16);          \
        }                                                                      \
    } while (0)

    CP_CHUNK(0, 0); CPCOMMIT();
    CP_CHUNK(1, 1); CPCOMMIT();

    // consumer lane addresses (ldmatrix: matrix i <- lanes 8i..8i+7 supply row ptrs)
    const int i4 = lane >> 3, r8 = lane & 7;
    // A: matrix0 rows+0 cols+0, m1 rows+8 cols+0, m2 rows+0 cols+4, m3 rows+8 cols+4
    const uint32_t a_off = ((uint32_t)(wm * 64 + ((i4 & 1) << 3) + r8) * 16
                           + (uint32_t)((i4 >> 1) << 2)) * 4;
    // B: matrix0 cols+0 (b0), matrix1 cols+4 (b1); rows = n-rows
    const uint32_t b_off = 8192 + ((uint32_t)(wn * 32 + r8) * 16
                           + (uint32_t)((i4 & 1) << 2)) * 4;

    float acc[4][4][4];
#pragma unroll
    for (int mt = 0; mt < 4; ++mt)
#pragma unroll
        for (int nt = 0; nt < 4; ++nt)
#pragma unroll
            for (int r = 0; r < 4; ++r) acc[mt][nt][r] = 0.f;

    for (int c = 0; c < NCHUNK; ++c) {
        CPWAIT1();
        __syncthreads();
        const int st = c % 3;
        if (c + 2 < NCHUNK) CP_CHUNK(c + 2, (c + 2) % 3);
        CPCOMMIT();

        const uint32_t abase = sb + (uint32_t)st * STAGE_B + a_off;
        const uint32_t bbase = sb + (uint32_t)st * STAGE_B + b_off;

#pragma unroll
        for (int ks = 0; ks < 2; ++ks) {
            uint32_t bh[4][2], bl[4][2];
#pragma unroll
            for (int nt = 0; nt < 4; ++nt) {
                uint32_t r0, r1;
                LDSM_X2(r0, r1, bbase + nt * 512 + ks * 32);
                float f0 = __uint_as_float(r0), f1 = __uint_as_float(r1);
                bh[nt][0] = cvt_tf32(f0);
                bl[nt][0] = cvt_tf32(f0 - __uint_as_float(bh[nt][0]));
                bh[nt][1] = cvt_tf32(f1);
                bl[nt][1] = cvt_tf32(f1 - __uint_as_float(bh[nt][1]));
            }
#pragma unroll
            for (int mt = 0; mt < 4; ++mt) {
                uint32_t a0, a1, a2, a3;
                LDSM_X4(a0, a1, a2, a3, abase + mt * 1024 + ks * 32);
                uint32_t ah[4], al[4];
                float fa;
                fa = __uint_as_float(a0); ah[0] = cvt_tf32(fa);
                al[0] = cvt_tf32(fa - __uint_as_float(ah[0]));
                fa = __uint_as_float(a1); ah[1] = cvt_tf32(fa);
                al[1] = cvt_tf32(fa - __uint_as_float(ah[1]));
                fa = __uint_as_float(a2); ah[2] = cvt_tf32(fa);
                al[2] = cvt_tf32(fa - __uint_as_float(ah[2]));
                fa = __uint_as_float(a3); ah[3] = cvt_tf32(fa);
                al[3] = cvt_tf32(fa - __uint_as_float(ah[3]));
#pragma unroll
                for (int nt = 0; nt < 4; ++nt) {
                    MMA_TF32(acc[mt][nt], ah, bl[nt][0], bl[nt][1]);   // hi*lo
                    MMA_TF32(acc[mt][nt], al, bh[nt][0], bh[nt][1]);   // lo*hi
                    MMA_TF32(acc[mt][nt], ah, bh[nt][0], bh[nt][1]);   // hi*hi
                }
            }
        }
    }

    // epilogue: D frag -> thread t owns rows t/4, t/4+8; cols 2*(t%4)+{0,1}
#pragma unroll
    for (int nt = 0; nt < 4; ++nt) {
        const int col = n0 + wn * 32 + nt * 8 + 2 * (lane & 3);
        const float bx = __ldg(&Bv[col]);
        const float by = __ldg(&Bv[col + 1]);
#pragma unroll
        for (int mt = 0; mt < 4; ++mt) {
            const int r0i = m0 + wm * 64 + mt * 16 + (lane >> 2);
            float2 v0 = make_float2(acc[mt][nt][0] + bx, acc[mt][nt][1] + by);
            float2 v1 = make_float2(acc[mt][nt][2] + bx, acc[mt][nt][3] + by);
            *(float2*)&Y[(size_t)r0i * E_DIM + col] = v0;
            *(float2*)&Y[(size_t)(r0i + 8) * E_DIM + col] = v1;
        }
    }
}

// ===================== Flash attention (causal) — unchanged from R4 =====================
#define ATTN_SMEM (3 * 64 * 64 * 4 + 64 * 68 * 4)   // 66560 B

__global__ __launch_bounds__(256) void attn_kernel(
    const float* __restrict__ Qp, const float* __restrict__ Kp,
    const float* __restrict__ Vp, float* __restrict__ Op)
{
    extern __shared__ float sm[];
    float* Qs = sm;
    float* Ks = sm + 64 * 64;
    float* Vs = sm + 2 * 64 * 64;
    float* Ps = sm + 3 * 64 * 64;

    const int i  = blockIdx.x;
    const int bh = blockIdx.y;
    const int b  = bh >> 4;
    const int h  = bh & 15;
    const int tid = threadIdx.x;
    const int rg = tid >> 4;
    const int cg = tid & 15;

    const size_t base = (size_t)b * S_LEN * E_DIM + (size_t)h * H_DIM;

#pragma unroll
    for (int l = 0; l < 4; ++l) {
        int idx = tid + l * 256;
        int row = idx >> 4;
        int c4  = idx & 15;
        float4 v = *(const float4*)&Qp[base + (size_t)(i * 64 + row) * E_DIM + c4 * 4];
        int sc4 = c4 ^ ((row >> 2) & 7);
        *(float4*)&Qs[row * 64 + sc4 * 4] = v;
    }

    float m_prev[4], l_sum[4], o[4][4];
#pragma unroll
    for (int a = 0; a < 4; ++a) {
        m_prev[a] = -INFINITY;
        l_sum[a] = 0.f;
#pragma unroll
        for (int bb = 0; bb < 4; ++bb) o[a][bb] = 0.f;
    }

    for (int j = 0; j <= i; ++j) {
        __syncthreads();
#pragma unroll
        for (int l = 0; l < 4; ++l) {
            int idx = tid + l * 256;
            int row = idx >> 4;
            int c4  = idx & 15;
            int sc4 = c4 ^ ((row >> 2) & 7);
            float4 kv4 = *(const float4*)&Kp[base + (size_t)(j * 64 + row) * E_DIM + c4 * 4];
            *(float4*)&Ks[row * 64 + sc4 * 4] = kv4;
            float4 vv4 = *(const float4*)&Vp[base + (size_t)(j * 64 + row) * E_DIM + c4 * 4];
            *(float4*)&Vs[row * 64 + sc4 * 4] = vv4;
        }
        __syncthreads();

        float acc[4][4];
#pragma unroll
        for (int a = 0; a < 4; ++a)
#pragma unroll
            for (int bb = 0; bb < 4; ++bb) acc[a][bb] = 0.f;

#pragma unroll
        for (int d4 = 0; d4 < 16; ++d4) {
            float4 qv[4], kv[4];
#pragma unroll
            for (int a = 0; a < 4; ++a)
                qv[a] = *(const float4*)&Qs[(rg * 4 + a) * 64 + (d4 ^ (rg & 7)) * 4];
#pragma unroll
            for (int bb = 0; bb < 4; ++bb)
                kv[bb] = *(const float4*)&Ks[(cg * 4 + bb) * 64 + (d4 ^ (cg & 7)) * 4];
#pragma unroll
            for (int a = 0; a < 4; ++a)
#pragma unroll
                for (int bb = 0; bb < 4; ++bb) {
                    acc[a][bb] = fmaf(qv[a].x, kv[bb].x, acc[a][bb]);
                    acc[a][bb] = fmaf(qv[a].y, kv[bb].y, acc[a][bb]);
                    acc[a][bb] = fmaf(qv[a].z, kv[bb].z, acc[a][bb]);
                    acc[a][bb] = fmaf(qv[a].w, kv[bb].w, acc[a][bb]);
                }
        }

        const bool diag = (j == i);
#pragma unroll
        for (int a = 0; a < 4; ++a) {
            float mloc = -INFINITY;
#pragma unroll
            for (int bb = 0; bb < 4; ++bb) {
                float s = acc[a][bb] * 0.125f;
                if (diag && (cg * 4 + bb) > (rg * 4 + a)) s = -INFINITY;
                acc[a][bb] = s;
                mloc = fmaxf(mloc, s);
            }
            mloc = fmaxf(mloc, __shfl_xor_sync(0xffffffffu, mloc, 1));
            mloc = fmaxf(mloc, __shfl_xor_sync(0xffffffffu, mloc, 2));
            mloc = fmaxf(mloc, __shfl_xor_sync(0xffffffffu, mloc, 4));
            mloc = fmaxf(mloc, __shfl_xor_sync(0xffffffffu, mloc, 8));

            float m_new = fmaxf(m_prev[a], mloc);
            float fac = (m_prev[a] == -INFINITY) ? 0.f : __expf(m_prev[a] - m_new);
            m_prev[a] = m_new;

            float ls = 0.f;
#pragma unroll
            for (int bb = 0; bb < 4; ++bb) {
                float p = __expf(acc[a][bb] - m_new);
                acc[a][bb] = p;
                ls += p;
            }
            ls += __shfl_xor_sync(0xffffffffu, ls, 1);
            ls += __shfl_xor_sync(0xffffffffu, ls, 2);
            ls += __shfl_xor_sync(0xffffffffu, ls, 4);
            ls += __shfl_xor_sync(0xffffffffu, ls, 8);

            l_sum[a] = l_sum[a] * fac + ls;
#pragma unroll
            for (int bb = 0; bb < 4; ++bb) o[a][bb] *= fac;

            *(float4*)&Ps[(rg * 4 + a) * 68 + cg * 4] =
                make_float4(acc[a][0], acc[a][1], acc[a][2], acc[a][3]);
        }
        __syncwarp();

#pragma unroll 4
        for (int jj = 0; jj < 64; ++jj) {
            float4 vv = *(const float4*)&Vs[jj * 64 + (cg ^ ((jj >> 2) & 7)) * 4];
            float p0 = Ps[(rg * 4 + 0) * 68 + jj];
            float p1 = Ps[(rg * 4 + 1) * 68 + jj];
            float p2 = Ps[(rg * 4 + 2) * 68 + jj];
            float p3 = Ps[(rg * 4 + 3) * 68 + jj];
            o[0][0] = fmaf(p0, vv.x, o[0][0]); o[0][1] = fmaf(p0, vv.y, o[0][1]);
            o[0][2] = fmaf(p0, vv.z, o[0][2]); o[0][3] = fmaf(p0, vv.w, o[0][3]);
            o[1][0] = fmaf(p1, vv.x, o[1][0]); o[1][1] = fmaf(p1, vv.y, o[1][1]);
            o[1][2] = fmaf(p1, vv.z, o[1][2]); o[1][3] = fmaf(p1, vv.w, o[1][3]);
            o[2][0] = fmaf(p2, vv.x, o[2][0]); o[2][1] = fmaf(p2, vv.y, o[2][1]);
            o[2][2] = fmaf(p2, vv.z, o[2][2]); o[2][3] = fmaf(p2, vv.w, o[2][3]);
            o[3][0] = fmaf(p3, vv.x, o[3][0]); o[3][1] = fmaf(p3, vv.y, o[3][1]);
            o[3][2] = fmaf(p3, vv.z, o[3][2]); o[3][3] = fmaf(p3, vv.w, o[3][3]);
        }
    }

#pragma unroll
    for (int a = 0; a < 4; ++a) {
        float inv = 1.f / l_sum[a];
        float4 r = make_float4(o[a][0] * inv, o[a][1] * inv, o[a][2] * inv, o[a][3] * inv);
        *(float4*)&Op[base + (size_t)(i * 64 + rg * 4 + a) * E_DIM + cg * 4] = r;
    }
}

// ===================== launch =====================
extern "C" void kernel_launch(void* const* d_in, const int* in_sizes, int n_in,
                              void* d_out, int out_size)
{
    (void)in_sizes; (void)n_in; (void)out_size;
    const float* q  = (const float*)d_in[0];
    const float* k  = (const float*)d_in[1];
    const float* v  = (const float*)d_in[2];
    const float* Wq = (const float*)d_in[3];
    const float* bq = (const float*)d_in[4];
    const float* Wk = (const float*)d_in[5];
    const float* bk = (const float*)d_in[6];
    const float* Wv = (const float*)d_in[7];
    const float* bv = (const float*)d_in[8];
    const float* Wo = (const float*)d_in[9];
    const float* bo = (const float*)d_in[10];
    float* out = (float*)d_out;

    float *gq, *gk, *gv, *go;
    cudaGetSymbolAddress((void**)&gq, g_q);
    cudaGetSymbolAddress((void**)&gk, g_k);
    cudaGetSymbolAddress((void**)&gv, g_v);
    cudaGetSymbolAddress((void**)&go, g_o);

    cudaFuncSetAttribute(gemm_tc_kernel, cudaFuncAttributeMaxDynamicSharedMemorySize, GEMM_SMEM);
    cudaFuncSetAttribute(attn_kernel, cudaFuncAttributeMaxDynamicSharedMemorySize, ATTN_SMEM);

    // Fused Q/K/V projections (z selects the triple).
    dim3 gridP(E_DIM / 128, M_ROWS / 128, 3);
    gemm_tc_kernel<<<gridP, 256, GEMM_SMEM>>>(q, k, v, Wq, Wk, Wv, bq, bk, bv, gq, gk, gv);

    // Causal flash attention.
    dim3 gridA(S_LEN / 64, N_BATCH * N_HEADS);
    attn_kernel<<<gridA, 256, ATTN_SMEM>>>(gq, gk, gv, go);

    // Output projection into d_out.
    dim3 gridO(E_DIM / 128, M_ROWS / 128, 1);
    gemm_tc_kernel<<<gridO, 256, GEMM_SMEM>>>(go, go, go, Wo, Wo, Wo, bo, bo, bo, out, out, out);
}

// round 7
// speedup vs baseline: 1.2584x; 1.1103x over previous
#include <cuda_runtime.h>
#include <math.h>
#include <stdint.h>

#define E_DIM   1024
#define S_LEN   2048
#define N_BATCH 2
#define N_HEADS 16
#define H_DIM   64
#define M_ROWS  (N_BATCH * S_LEN)   // 4096

// Scratch (allocation-free). g_v holds V^T in [b*16+h][d][s] layout (written by the
// V-projection epilogue); g_q/g_k normal [token][h*64+d]; g_o attention output.
__device__ float g_q[(size_t)M_ROWS * E_DIM];
__device__ float g_k[(size_t)M_ROWS * E_DIM];
__device__ float g_v[(size_t)M_ROWS * E_DIM];
__device__ float g_o[(size_t)M_ROWS * E_DIM];

// ===================== helpers =====================
__device__ __forceinline__ uint32_t smem_u32(const void* p) {
    uint32_t a;
    asm("{ .reg .u64 t; cvta.to.shared.u64 t, %1; cvt.u32.u64 %0, t; }" : "=r"(a) : "l"(p));
    return a;
}
__device__ __forceinline__ uint32_t cvt_tf32(float f) {
    uint32_t u;
    asm("cvt.rna.tf32.f32 %0, %1;" : "=r"(u) : "f"(f));
    return u;
}
__device__ __forceinline__ void split2(uint32_t r, uint32_t& hi, uint32_t& lo) {
    float f = __uint_as_float(r);
    hi = cvt_tf32(f);
    lo = cvt_tf32(f - __uint_as_float(hi));
}

#define CP16(dst, src) \
    asm volatile("cp.async.cg.shared.global [%0], [%1], 16;" :: "r"(dst), "l"(src))
#define CPCOMMIT() asm volatile("cp.async.commit_group;" ::: "memory")
#define CPWAIT1()  asm volatile("cp.async.wait_group 1;" ::: "memory")
#define CPWAIT0()  asm volatile("cp.async.wait_group 0;" ::: "memory")

#define LDSM_X4(r0, r1, r2, r3, addr)                                          \
    asm volatile("ldmatrix.sync.aligned.m8n8.x4.shared.b16 {%0,%1,%2,%3}, [%4];" \
                 : "=r"(r0), "=r"(r1), "=r"(r2), "=r"(r3) : "r"(addr))
#define LDSM_X2(r0, r1, addr)                                                  \
    asm volatile("ldmatrix.sync.aligned.m8n8.x2.shared.b16 {%0,%1}, [%2];"     \
                 : "=r"(r0), "=r"(r1) : "r"(addr))

#define MMA_TF32(d, A, b0v, b1v)                                               \
    asm volatile("mma.sync.aligned.m16n8k8.row.col.f32.tf32.tf32.f32 "         \
                 "{%0,%1,%2,%3}, {%4,%5,%6,%7}, {%8,%9}, {%0,%1,%2,%3};"       \
                 : "+f"((d)[0]), "+f"((d)[1]), "+f"((d)[2]), "+f"((d)[3])      \
                 : "r"((A)[0]), "r"((A)[1]), "r"((A)[2]), "r"((A)[3]),         \
                   "r"(b0v), "r"(b1v))

#define STS64(addr, v0, v1) \
    asm volatile("st.shared.v2.f32 [%0], {%1,%2};" :: "r"(addr), "f"(v0), "f"(v1))

// ===================== mma.sync TF32-split GEMM: Y = X @ W^T + b =====================
// CTA 128x128, 8 warps (2m x 4n), warp tile 64x32. K chunk 16, cp.async 3-stage.
// smem rows: 16 floats with 80B stride (5*16B -> rows rotate over all 8 bank groups,
// conflict-free ldmatrix). z==2 writes V^T layout to YT instead of Y.
#define NCHUNK   (E_DIM / 16)         // 64
#define ROWB     80                   // bytes per 16-float row
#define MATB     (128 * ROWB)         // 10240 per matrix tile
#define STAGE_B  (2 * MATB)           // 20480
#define GEMM_SMEM (3 * STAGE_B)       // 61440

__global__ __launch_bounds__(256) void gemm_tc_kernel(
    const float* __restrict__ X0, const float* __restrict__ X1, const float* __restrict__ X2,
    const float* __restrict__ W0, const float* __restrict__ W1, const float* __restrict__ W2,
    const float* __restrict__ B0, const float* __restrict__ B1, const float* __restrict__ B2,
    float* __restrict__ Y0, float* __restrict__ Y1, float* __restrict__ Y2,
    float* __restrict__ YT)
{
    extern __shared__ char smem[];
    const int z = blockIdx.z;
    const float* __restrict__ X  = (z == 0) ? X0 : ((z == 1) ? X1 : X2);
    const float* __restrict__ W  = (z == 0) ? W0 : ((z == 1) ? W1 : W2);
    const float* __restrict__ Bv = (z == 0) ? B0 : ((z == 1) ? B1 : B2);
    float* __restrict__ Y        = (z == 0) ? Y0 : ((z == 1) ? Y1 : Y2);

    const int tid  = threadIdx.x;
    const int lane = tid & 31;
    const int wid  = tid >> 5;
    const int wm   = wid >> 2;
    const int wn   = wid & 3;
    const int m0 = blockIdx.y * 128;
    const int n0 = blockIdx.x * 128;

    const uint32_t sb = smem_u32(smem);

    const int prow = tid >> 2;
    const int pc4  = tid & 3;
    const float* Xsrc = &X[(size_t)(m0 + prow) * E_DIM + pc4 * 4];
    const float* Wsrc = &W[(size_t)(n0 + prow) * E_DIM + pc4 * 4];
    const uint32_t pdst = sb + (uint32_t)prow * ROWB + (uint32_t)pc4 * 16;

    #define CP_CHUNK(c, st) do {                                               \
        _Pragma("unroll")                                                      \
        for (int q = 0; q < 2; ++q) {                                          \
            uint32_t d = pdst + (uint32_t)(st) * STAGE_B + q * (64 * ROWB);    \
            CP16(d,        Xsrc + (size_t)q * 64 * E_DIM + (c) * 16);          \
            CP16(d + MATB, Wsrc + (size_t)q * 64 * E_DIM + (c) * 16);          \
        }                                                                      \
    } while (0)

    CP_CHUNK(0, 0); CPCOMMIT();
    CP_CHUNK(1, 1); CPCOMMIT();

    const int i4 = lane >> 3, r8 = lane & 7;
    const uint32_t a_off = (uint32_t)(wm * 64 + ((i4 & 1) << 3) + r8) * ROWB
                         + (uint32_t)((i4 >> 1) << 4);
    const uint32_t b_off = MATB + (uint32_t)(wn * 32 + r8) * ROWB
                         + (uint32_t)((i4 & 1) << 4);

    float acc[4][4][4];
#pragma unroll
    for (int mt = 0; mt < 4; ++mt)
#pragma unroll
        for (int nt = 0; nt < 4; ++nt)
#pragma unroll
            for (int r = 0; r < 4; ++r) acc[mt][nt][r] = 0.f;

    for (int c = 0; c < NCHUNK; ++c) {
        CPWAIT1();
        __syncthreads();
        const int st = c % 3;
        if (c + 2 < NCHUNK) CP_CHUNK(c + 2, (c + 2) % 3);
        CPCOMMIT();

        const uint32_t abase = sb + (uint32_t)st * STAGE_B + a_off;
        const uint32_t bbase = sb + (uint32_t)st * STAGE_B + b_off;

#pragma unroll
        for (int ks = 0; ks < 2; ++ks) {
            uint32_t bh[4][2], bl[4][2];
#pragma unroll
            for (int nt = 0; nt < 4; ++nt) {
                uint32_t r0, r1;
                LDSM_X2(r0, r1, bbase + nt * (8 * ROWB) + ks * 32);
                split2(r0, bh[nt][0], bl[nt][0]);
                split2(r1, bh[nt][1], bl[nt][1]);
            }
#pragma unroll
            for (int mt = 0; mt < 4; ++mt) {
                uint32_t a0, a1, a2, a3;
                LDSM_X4(a0, a1, a2, a3, abase + mt * (16 * ROWB) + ks * 32);
                uint32_t ah[4], al[4];
                split2(a0, ah[0], al[0]);
                split2(a1, ah[1], al[1]);
                split2(a2, ah[2], al[2]);
                split2(a3, ah[3], al[3]);
#pragma unroll
                for (int nt = 0; nt < 4; ++nt) {
                    MMA_TF32(acc[mt][nt], ah, bl[nt][0], bl[nt][1]);
                    MMA_TF32(acc[mt][nt], al, bh[nt][0], bh[nt][1]);
                    MMA_TF32(acc[mt][nt], ah, bh[nt][0], bh[nt][1]);
                }
            }
        }
    }

    if (z == 2) {
        // V^T epilogue: YT[(b*16+h)*64 + d][s] = acc + bias
        const int bq = m0 >> 11;
#pragma unroll
        for (int nt = 0; nt < 4; ++nt) {
            const int col = n0 + wn * 32 + nt * 8 + 2 * (lane & 3);
            const int hh = col >> 6, dd = col & 63;
            const float bx = __ldg(&Bv[col]);
            const float by = __ldg(&Bv[col + 1]);
            float* base0 = &YT[((size_t)(bq * 16 + hh) * 64 + dd) * S_LEN];
            float* base1 = base0 + S_LEN;
#pragma unroll
            for (int mt = 0; mt < 4; ++mt) {
                const int s = (m0 & 2047) + wm * 64 + mt * 16 + (lane >> 2);
                base0[s]     = acc[mt][nt][0] + bx;
                base1[s]     = acc[mt][nt][1] + by;
                base0[s + 8] = acc[mt][nt][2] + bx;
                base1[s + 8] = acc[mt][nt][3] + by;
            }
        }
    } else {
#pragma unroll
        for (int nt = 0; nt < 4; ++nt) {
            const int col = n0 + wn * 32 + nt * 8 + 2 * (lane & 3);
            const float bx = __ldg(&Bv[col]);
            const float by = __ldg(&Bv[col + 1]);
#pragma unroll
            for (int mt = 0; mt < 4; ++mt) {
                const int r0i = m0 + wm * 64 + mt * 16 + (lane >> 2);
                float2 v0 = make_float2(acc[mt][nt][0] + bx, acc[mt][nt][1] + by);
                float2 v1 = make_float2(acc[mt][nt][2] + bx, acc[mt][nt][3] + by);
                *(float2*)&Y[(size_t)r0i * E_DIM + col] = v0;
                *(float2*)&Y[(size_t)(r0i + 8) * E_DIM + col] = v1;
            }
        }
    }
}

// ===================== Tensorized causal flash attention =====================
// CTA: 64 q-rows x one (b,h). 4 warps x 16 rows. j loop over 64-wide KV tiles.
// smem: Qs(16K) | stage0{K,VT}(32K) | stage1{K,VT}(32K) | P per warp (4x4K).
// Rows = 64 floats = 16x16B slots, XOR swizzle slot^(row&7) -> conflict-free LDSM.
#define AQ_OFF   0u
#define AK_OFF   16384u
#define AV_OFF   32768u
#define AST_B    32768u
#define AP_OFF   81920u
#define ATTN_SMEM 98304

__global__ __launch_bounds__(128) void attn_tc_kernel(
    const float* __restrict__ Qp, const float* __restrict__ Kp,
    const float* __restrict__ VTp, float* __restrict__ Op)
{
    extern __shared__ char smem[];
    const uint32_t sb = smem_u32(smem);
    const int tid = threadIdx.x, lane = tid & 31, w = tid >> 5;
    const int i = blockIdx.x, bh = blockIdx.y;
    const int b = bh >> 4, h = bh & 15;

    const size_t qbase  = ((size_t)b * S_LEN + i * 64) * E_DIM + h * 64;
    const size_t kbase  = (size_t)b * S_LEN * E_DIM + h * 64;
    const size_t vtbase = (size_t)bh * 64 * S_LEN;

    // Q tile (once)
#pragma unroll
    for (int l = 0; l < 8; ++l) {
        int idx = tid + l * 128, row = idx >> 4, sl = idx & 15;
        CP16(sb + AQ_OFF + row * 256 + (((sl) ^ (row & 7)) << 4),
             Qp + qbase + (size_t)row * E_DIM + sl * 4);
    }

    #define ISSUE_KV(j_, st_) do {                                             \
        _Pragma("unroll")                                                      \
        for (int l = 0; l < 8; ++l) {                                          \
            int idx_ = tid + l * 128, row_ = idx_ >> 4, sl_ = idx_ & 15;       \
            uint32_t sw_ = (uint32_t)(row_ * 256 + (((sl_) ^ (row_ & 7)) << 4)); \
            CP16(sb + AK_OFF + (uint32_t)(st_) * AST_B + sw_,                  \
                 Kp + kbase + (size_t)((j_) * 64 + row_) * E_DIM + sl_ * 4);   \
            CP16(sb + AV_OFF + (uint32_t)(st_) * AST_B + sw_,                  \
                 VTp + vtbase + (size_t)row_ * S_LEN + (j_) * 64 + sl_ * 4);   \
        }                                                                      \
    } while (0)

    ISSUE_KV(0, 0);
    CPCOMMIT();

    const int i4 = lane >> 3, r8 = lane & 7;
    const int lr = lane >> 2;            // local row within warp tile (and +8)
    const int lc0 = 2 * (lane & 3);
    const int qrow = w * 16 + ((i4 & 1) << 3) + r8;
    const uint32_t qrb = sb + AQ_OFF + qrow * 256;
    const int qrm = qrow & 7;
    const int prow = ((i4 & 1) << 3) + r8;
    const uint32_t prb = sb + AP_OFF + (uint32_t)w * 4096 + prow * 256;
    const int prm = prow & 7;
    const uint32_t pw = sb + AP_OFF + (uint32_t)w * 4096;
    const int lrow0 = w * 16 + lr;       // local q row of regs 0,1 (d0,d1); +8 for d2,d3

    float m_prev0 = -INFINITY, m_prev1 = -INFINITY;
    float lsum0 = 0.f, lsum1 = 0.f;
    float o[8][4];
#pragma unroll
    for (int nt = 0; nt < 8; ++nt)
#pragma unroll
        for (int r = 0; r < 4; ++r) o[nt][r] = 0.f;

    for (int j = 0; j <= i; ++j) {
        CPWAIT0();
        __syncthreads();
        if (j < i) ISSUE_KV(j + 1, (j + 1) & 1);
        CPCOMMIT();

        const uint32_t kb  = sb + AK_OFF + (uint32_t)(j & 1) * AST_B;
        const uint32_t vtb = sb + AV_OFF + (uint32_t)(j & 1) * AST_B;

        // ---- S = Q K^T (3-split tf32) ----
        float sacc[8][4];
#pragma unroll
        for (int nt = 0; nt < 8; ++nt)
#pragma unroll
            for (int r = 0; r < 4; ++r) sacc[nt][r] = 0.f;

#pragma unroll
        for (int ks = 0; ks < 8; ++ks) {
            uint32_t a0, a1, a2, a3;
            LDSM_X4(a0, a1, a2, a3, qrb + ((((ks << 1) | (i4 >> 1)) ^ qrm) << 4));
            uint32_t ah[4], al[4];
            split2(a0, ah[0], al[0]); split2(a1, ah[1], al[1]);
            split2(a2, ah[2], al[2]); split2(a3, ah[3], al[3]);
#pragma unroll
            for (int nt = 0; nt < 8; ++nt) {
                const int brow = (nt << 3) | r8;
                uint32_t b0, b1;
                LDSM_X2(b0, b1, kb + brow * 256 + ((((ks << 1) | (i4 & 1)) ^ (brow & 7)) << 4));
                uint32_t bh0, bl0, bh1, bl1;
                split2(b0, bh0, bl0); split2(b1, bh1, bl1);
                MMA_TF32(sacc[nt], ah, bl0, bl1);
                MMA_TF32(sacc[nt], al, bh0, bh1);
                MMA_TF32(sacc[nt], ah, bh0, bh1);
            }
        }

        // ---- online softmax ----
        const bool diag = (j == i);
        float mloc0 = -INFINITY, mloc1 = -INFINITY;
#pragma unroll
        for (int nt = 0; nt < 8; ++nt) {
            const int c0 = (nt << 3) + lc0;
            float s0 = sacc[nt][0] * 0.125f, s1 = sacc[nt][1] * 0.125f;
            float s2 = sacc[nt][2] * 0.125f, s3 = sacc[nt][3] * 0.125f;
            if (diag) {
                if (c0     > lrow0)     s0 = -INFINITY;
                if (c0 + 1 > lrow0)     s1 = -INFINITY;
                if (c0     > lrow0 + 8) s2 = -INFINITY;
                if (c0 + 1 > lrow0 + 8) s3 = -INFINITY;
            }
            sacc[nt][0] = s0; sacc[nt][1] = s1; sacc[nt][2] = s2; sacc[nt][3] = s3;
            mloc0 = fmaxf(mloc0, fmaxf(s0, s1));
            mloc1 = fmaxf(mloc1, fmaxf(s2, s3));
        }
        mloc0 = fmaxf(mloc0, __shfl_xor_sync(0xffffffffu, mloc0, 1));
        mloc0 = fmaxf(mloc0, __shfl_xor_sync(0xffffffffu, mloc0, 2));
        mloc1 = fmaxf(mloc1, __shfl_xor_sync(0xffffffffu, mloc1, 1));
        mloc1 = fmaxf(mloc1, __shfl_xor_sync(0xffffffffu, mloc1, 2));

        const float m_new0 = fmaxf(m_prev0, mloc0);
        const float m_new1 = fmaxf(m_prev1, mloc1);
        const float fac0 = (m_prev0 == -INFINITY) ? 0.f : __expf(m_prev0 - m_new0);
        const float fac1 = (m_prev1 == -INFINITY) ? 0.f : __expf(m_prev1 - m_new1);
        m_prev0 = m_new0; m_prev1 = m_new1;

        float ls0 = 0.f, ls1 = 0.f;
        const int pslot_lo = (lane & 3) >> 1;
        const uint32_t pword = (uint32_t)((lane & 1) << 3);
#pragma unroll
        for (int nt = 0; nt < 8; ++nt) {
            float p0 = __expf(sacc[nt][0] - m_new0);
            float p1 = __expf(sacc[nt][1] - m_new0);
            float p2 = __expf(sacc[nt][2] - m_new1);
            float p3 = __expf(sacc[nt][3] - m_new1);
            ls0 += p0 + p1;
            ls1 += p2 + p3;
            const int slot = (nt << 1) | pslot_lo;
            STS64(pw + lr * 256 + ((slot ^ (lr & 7)) << 4) + pword, p0, p1);
            STS64(pw + (lr + 8) * 256 + ((slot ^ ((lr + 8) & 7)) << 4) + pword, p2, p3);
        }
        ls0 += __shfl_xor_sync(0xffffffffu, ls0, 1);
        ls0 += __shfl_xor_sync(0xffffffffu, ls0, 2);
        ls1 += __shfl_xor_sync(0xffffffffu, ls1, 1);
        ls1 += __shfl_xor_sync(0xffffffffu, ls1, 2);
        lsum0 = lsum0 * fac0 + ls0;
        lsum1 = lsum1 * fac1 + ls1;

#pragma unroll
        for (int nt = 0; nt < 8; ++nt) {
            o[nt][0] *= fac0; o[nt][1] *= fac0;
            o[nt][2] *= fac1; o[nt][3] *= fac1;
        }
        __syncwarp();

        // ---- O += P V (3-split tf32) ----
#pragma unroll
        for (int ks = 0; ks < 8; ++ks) {
            uint32_t a0, a1, a2, a3;
            LDSM_X4(a0, a1, a2, a3, prb + ((((ks << 1) | (i4 >> 1)) ^ prm) << 4));
            uint32_t ah[4], al[4];
            split2(a0, ah[0], al[0]); split2(a1, ah[1], al[1]);
            split2(a2, ah[2], al[2]); split2(a3, ah[3], al[3]);
#pragma unroll
            for (int nt = 0; nt < 8; ++nt) {
                const int vrow = (nt << 3) | r8;
                uint32_t b0, b1;
                LDSM_X2(b0, b1, vtb + vrow * 256 + ((((ks << 1) | (i4 & 1)) ^ (vrow & 7)) << 4));
                uint32_t bh0, bl0, bh1, bl1;
                split2(b0, bh0, bl0); split2(b1, bh1, bl1);
                MMA_TF32(o[nt], ah, bl0, bl1);
                MMA_TF32(o[nt], al, bh0, bh1);
                MMA_TF32(o[nt], ah, bh0, bh1);
            }
        }
        __syncwarp();   // P reads done before next iter's P stores
    }

    // ---- epilogue ----
    const float inv0 = 1.f / lsum0;
    const float inv1 = 1.f / lsum1;
    const size_t orow = (size_t)b * S_LEN + i * 64 + w * 16 + lr;
#pragma unroll
    for (int nt = 0; nt < 8; ++nt) {
        const int col = h * 64 + (nt << 3) + lc0;
        float2 v0 = make_float2(o[nt][0] * inv0, o[nt][1] * inv0);
        float2 v1 = make_float2(o[nt][2] * inv1, o[nt][3] * inv1);
        *(float2*)&Op[orow * E_DIM + col] = v0;
        *(float2*)&Op[(orow + 8) * E_DIM + col] = v1;
    }
}

// ===================== launch =====================
extern "C" void kernel_launch(void* const* d_in, const int* in_sizes, int n_in,
                              void* d_out, int out_size)
{
    (void)in_sizes; (void)n_in; (void)out_size;
    const float* q  = (const float*)d_in[0];
    const float* k  = (const float*)d_in[1];
    const float* v  = (const float*)d_in[2];
    const float* Wq = (const float*)d_in[3];
    const float* bq = (const float*)d_in[4];
    const float* Wk = (const float*)d_in[5];
    const float* bk = (const float*)d_in[6];
    const float* Wv = (const float*)d_in[7];
    const float* bv = (const float*)d_in[8];
    const float* Wo = (const float*)d_in[9];
    const float* bo = (const float*)d_in[10];
    float* out = (float*)d_out;

    float *gq, *gk, *gv, *go;
    cudaGetSymbolAddress((void**)&gq, g_q);
    cudaGetSymbolAddress((void**)&gk, g_k);
    cudaGetSymbolAddress((void**)&gv, g_v);
    cudaGetSymbolAddress((void**)&go, g_o);

    cudaFuncSetAttribute(gemm_tc_kernel, cudaFuncAttributeMaxDynamicSharedMemorySize, GEMM_SMEM);
    cudaFuncSetAttribute(attn_tc_kernel, cudaFuncAttributeMaxDynamicSharedMemorySize, ATTN_SMEM);

    // Q/K/V projections; z==2 (V) writes V^T [bh][d][s] into gv.
    dim3 gridP(E_DIM / 128, M_ROWS / 128, 3);
    gemm_tc_kernel<<<gridP, 256, GEMM_SMEM>>>(q, k, v, Wq, Wk, Wv, bq, bk, bv,
                                              gq, gk, gv, gv);

    // Tensorized causal flash attention.
    dim3 gridA(S_LEN / 64, N_BATCH * N_HEADS);
    attn_tc_kernel<<<gridA, 128, ATTN_SMEM>>>(gq, gk, gv, go);

    // Output projection into d_out.
    dim3 gridO(E_DIM / 128, M_ROWS / 128, 1);
    gemm_tc_kernel<<<gridO, 256, GEMM_SMEM>>>(go, go, go, Wo, Wo, Wo, bo, bo, bo,
                                              out, out, out, nullptr);
}